// round 11
// baseline (speedup 1.0000x reference)
#include <cuda_runtime.h>
#include <cuda_fp16.h>
#include <cstdint>
#include <math.h>

#define BATCH 16
#define NNODE 512
#define IDIM  512
#define HDIM  1024

#define RNB 296          // persistent blocks, occupancy 2
#define RNT 256

// ---------------- device scratch ----------------
__device__ __half g_Vh[3u * HDIM * HDIM];         // V_g fp16 [g][n][k] (symmetric)
__device__ __half g_hph[BATCH * NNODE * HDIM];    // fp16 mirror of tree_h (A operand)
__device__ float  g_inp0f[BATCH * HDIM];
__device__ float  g_inp0o[BATCH * HDIM];
__device__ float  g_inp0z[BATCH * HDIM];
__device__ float  g_tree_c[BATCH * NNODE * HDIM];
__device__ int    g_sched[BATCH * NNODE];
__device__ int    g_level_off[NNODE + 1];
__device__ int    g_num_levels;
__device__ unsigned int g_bar;

// ---------------- helpers ----------------
__device__ __forceinline__ void mma_tf32(float* d, const uint32_t* a, const uint32_t* b) {
    asm volatile(
        "mma.sync.aligned.m16n8k8.row.col.f32.tf32.tf32.f32 "
        "{%0,%1,%2,%3}, {%4,%5,%6,%7}, {%8,%9}, {%0,%1,%2,%3};\n"
        : "+f"(d[0]), "+f"(d[1]), "+f"(d[2]), "+f"(d[3])
        : "r"(a[0]), "r"(a[1]), "r"(a[2]), "r"(a[3]), "r"(b[0]), "r"(b[1]));
}
__device__ __forceinline__ void mma_f16(float* d, const uint32_t* a, const uint32_t* b) {
    asm volatile(
        "mma.sync.aligned.m16n8k16.row.col.f32.f16.f16.f32 "
        "{%0,%1,%2,%3}, {%4,%5,%6,%7}, {%8,%9}, {%0,%1,%2,%3};\n"
        : "+f"(d[0]), "+f"(d[1]), "+f"(d[2]), "+f"(d[3])
        : "r"(a[0]), "r"(a[1]), "r"(a[2]), "r"(a[3]), "r"(b[0]), "r"(b[1]));
}
__device__ __forceinline__ float sigf(float x) {
    return __fdividef(1.0f, 1.0f + __expf(-x));
}
__device__ __forceinline__ float tanf_(float x) {
    return 1.0f - __fdividef(2.0f, 1.0f + __expf(2.0f * x));
}

// ---------------- setup: reset + levels + counting sort ----------------
__global__ void setup_kernel(const int* __restrict__ conn) {
    __shared__ unsigned short lvl[BATCH][NNODE];
    __shared__ int counts[NNODE];
    __shared__ int offs[NNODE + 1];
    __shared__ int cur[NNODE];
    int tid = threadIdx.x;
    if (tid == 0) g_bar = 0u;
    for (int l = tid; l < NNODE; l += blockDim.x) counts[l] = 0;
    __syncthreads();
    if (tid < BATCH) {
        int b = tid;
        lvl[b][0] = 0;
        for (int i = 1; i < NNODE; i++) {
            int p = conn[b * NNODE + i];
            lvl[b][i] = (unsigned short)(lvl[b][p] + 1);
        }
    }
    __syncthreads();
    for (int t = tid; t < BATCH * NNODE; t += blockDim.x) {
        int i = t & (NNODE - 1);
        if (i != 0) atomicAdd(&counts[lvl[t >> 9][i]], 1);
    }
    __syncthreads();
    if (tid == 0) {
        int acc = 0, maxl = 0;
        for (int l = 0; l < NNODE; l++) {
            offs[l] = acc;
            acc += counts[l];
            if (counts[l] > 0) maxl = l;
        }
        offs[NNODE] = acc;
        g_num_levels = maxl + 1;
    }
    __syncthreads();
    for (int l = tid; l <= NNODE; l += blockDim.x) g_level_off[l] = offs[l];
    for (int l = tid; l < NNODE; l += blockDim.x) cur[l] = offs[l];
    __syncthreads();
    for (int t = tid; t < BATCH * NNODE; t += blockDim.x) {
        int b = t >> 9, i = t & (NNODE - 1);
        if (i != 0) {
            int pos = atomicAdd(&cur[lvl[b][i]], 1);
            g_sched[pos] = (b << 16) | i;
        }
    }
}

// ---------------- inp0 (only node 0 matters) + roots ----------------
__global__ void inp0_kernel(const float* __restrict__ emb,
                            const float* __restrict__ Wf, const float* __restrict__ bf,
                            const float* __restrict__ Wo, const float* __restrict__ bo,
                            const float* __restrict__ Wz, const float* __restrict__ bz,
                            float* __restrict__ tree_h) {
    int t = blockIdx.x * blockDim.x + threadIdx.x;
    int b = t >> 10, n = t & (HDIM - 1);
    const float* x = emb + (size_t)b * NNODE * IDIM;
    float af = bf[n], ao = bo[n], az = bz[n];
#pragma unroll 8
    for (int k = 0; k < IDIM; k++) {
        float xv = __ldg(&x[k]);
        af = fmaf(xv, Wf[k * HDIM + n], af);
        ao = fmaf(xv, Wo[k * HDIM + n], ao);
        az = fmaf(xv, Wz[k * HDIM + n], az);
    }
    g_inp0f[t] = af; g_inp0o[t] = ao; g_inp0z[t] = az;
    float f = 1.0f / (1.0f + expf(-af));
    float o = 1.0f / (1.0f + expf(-ao));
    float z = tanhf(az);
    float c = z * (1.0f - f);
    float h = o * tanhf(c);
    int row = (b * NNODE) << 10;
    tree_h[row + n] = h;
    g_hph[row + n] = __float2half(h);
    g_tree_c[row + n] = c;
}

// ---------------- V = T^T T, upper-triangular tiles + mirror (symmetric) ----
#define NTRI 136
__global__ void v_kernel(const float* __restrict__ Tf,
                         const float* __restrict__ To,
                         const float* __restrict__ Tz) {
    __shared__ float Ats[32][68];
    __shared__ float Bts[32][68];
    int bid = blockIdx.x;
    int g = bid / NTRI;
    int t = bid - g * NTRI;
    int ti = 0;
    while (t >= 16 - ti) { t -= 16 - ti; ti++; }
    int tj = ti + t;
    int m0 = ti << 6, n0 = tj << 6;
    const float* T = (g == 0) ? Tf : (g == 1) ? To : Tz;
    int tid = threadIdx.x, lane = tid & 31, wid = tid >> 5;
    int moff = (wid >> 2) << 5, noff = (wid & 3) << 4;

    float acc[2][2][4];
#pragma unroll
    for (int mf = 0; mf < 2; mf++)
#pragma unroll
        for (int nf = 0; nf < 2; nf++)
#pragma unroll
            for (int j = 0; j < 4; j++) acc[mf][nf][j] = 0.0f;

    for (int k0 = 0; k0 < HDIM; k0 += 32) {
#pragma unroll
        for (int q = 0; q < 2; q++) {
            int fi = tid + (q << 8);
            int kk = fi >> 4, c4 = fi & 15;
            const float* rowp = T + (size_t)(k0 + kk) * HDIM;
            *(float4*)&Ats[kk][c4 << 2] = *(const float4*)(rowp + m0 + (c4 << 2));
            *(float4*)&Bts[kk][c4 << 2] = *(const float4*)(rowp + n0 + (c4 << 2));
        }
        __syncthreads();
#pragma unroll
        for (int ks = 0; ks < 4; ks++) {
            int kb = ks << 3;
            uint32_t a[2][4], b[2][2];
#pragma unroll
            for (int mf = 0; mf < 2; mf++)
#pragma unroll
                for (int i = 0; i < 4; i++) {
                    int m = moff + (mf << 4) + (lane >> 2) + ((i & 1) << 3);
                    int k = kb + (lane & 3) + ((i >> 1) << 2);
                    a[mf][i] = __float_as_uint(Ats[k][m]);
                }
#pragma unroll
            for (int nf = 0; nf < 2; nf++)
#pragma unroll
                for (int i = 0; i < 2; i++) {
                    int n = noff + (nf << 3) + (lane >> 2);
                    int k = kb + (lane & 3) + (i << 2);
                    b[nf][i] = __float_as_uint(Bts[k][n]);
                }
#pragma unroll
            for (int mf = 0; mf < 2; mf++)
#pragma unroll
                for (int nf = 0; nf < 2; nf++)
                    mma_tf32(acc[mf][nf], a[mf], b[nf]);
        }
        __syncthreads();
    }
    size_t gb = (size_t)g << 20;
#pragma unroll
    for (int mf = 0; mf < 2; mf++)
#pragma unroll
        for (int nf = 0; nf < 2; nf++)
#pragma unroll
            for (int rh = 0; rh < 2; rh++) {
                int m = m0 + moff + (mf << 4) + (lane >> 2) + (rh << 3);
                int n = n0 + noff + (nf << 3) + ((lane & 3) << 1);
                float v0 = acc[mf][nf][rh << 1], v1 = acc[mf][nf][(rh << 1) + 1];
                *(__half2*)&g_Vh[gb + ((size_t)m << 10) + n] = __floats2half2_rn(v0, v1);
                if (ti != tj) {
                    g_Vh[gb + ((size_t)n << 10) + m]       = __float2half(v0);
                    g_Vh[gb + ((size_t)(n + 1) << 10) + m] = __float2half(v1);
                }
            }
}

// ---------------- persistent recurrence: M=32 x N=32, intra-CTA K-split ----
// Warp (ks = wid>>1 in 0..3, mf = wid&1): m16 x n32 x 3 gates over K=256.
// Fragments loaded directly from L2 (no smem staging, no mainloop syncs).
__global__ void __launch_bounds__(RNT, 2)
recur_kernel(const int* __restrict__ conn, float* __restrict__ tree_h) {
    __shared__ float red[2][32][49];      // [mf][lane][48], pad -> conflict-free
    __shared__ int s_prow[32];
    __shared__ int s_irow[32];
    __shared__ int s_bn[32];

    int tid = threadIdx.x, lane = tid & 31, wid = tid >> 5;
    int mf = wid & 1, ks = wid >> 1;
    int g8 = lane >> 2, t2 = (lane & 3) << 1;
    int jg = wid >> 1;                    // epilogue n8-group (0..3)

    int num_lv = g_num_levels;
    unsigned sync_no = 0;

    for (int lv = 1; lv < num_lv; lv++) {
        int off = g_level_off[lv];
        int cnt = g_level_off[lv + 1] - off;
        int mtiles = (cnt + 31) >> 5;
        int total = mtiles << 5;                 // x 32 column slices of 32

        for (int t = blockIdx.x; t < total; t += RNB) {
            int mt = t >> 5, nt = t & 31;
            int n0 = nt << 5;
            int mrel = mt << 5;

            if (tid < 32) {
                int mi = off + mrel + tid;
                int mclamp = off + cnt - 1;
                if (mi > mclamp) mi = mclamp;
                int s = g_sched[mi];
                int b = s >> 16, i = s & 0xFFFF;
                int p = conn[(b << 9) + i];
                s_prow[tid] = ((b << 9) + p) << 10;
                s_irow[tid] = ((b << 9) + i) << 10;
                s_bn[tid]   = b << 10;
            }
            __syncthreads();

            // ---- mainloop: warp-private K segment, direct-LDG fragments ----
            int r0 = (mf << 4) + g8;
            int prow0 = s_prow[r0], prow1 = s_prow[r0 + 8];
            int vrow[4];
#pragma unroll
            for (int j = 0; j < 4; j++) vrow[j] = (n0 + (j << 3) + g8) << 10;

            float acc[3][4][4];
#pragma unroll
            for (int g = 0; g < 3; g++)
#pragma unroll
                for (int j = 0; j < 4; j++)
#pragma unroll
                    for (int q = 0; q < 4; q++) acc[g][j][q] = 0.0f;

            int kbase = (ks << 8) + t2;
            const __half* Ap0 = g_hph + prow0 + kbase;
            const __half* Ap1 = g_hph + prow1 + kbase;
            const __half* Vp  = g_Vh + kbase;

#pragma unroll 4
            for (int s = 0; s < 16; s++) {
                int ko = s << 4;
                uint32_t a[4];
                a[0] = *(const uint32_t*)(Ap0 + ko);
                a[1] = *(const uint32_t*)(Ap1 + ko);
                a[2] = *(const uint32_t*)(Ap0 + ko + 8);
                a[3] = *(const uint32_t*)(Ap1 + ko + 8);
#pragma unroll
                for (int g = 0; g < 3; g++) {
                    const __half* Vg = Vp + ((size_t)g << 20) + ko;
                    uint32_t b[4][2];
#pragma unroll
                    for (int j = 0; j < 4; j++) {
                        b[j][0] = *(const uint32_t*)(Vg + vrow[j]);
                        b[j][1] = *(const uint32_t*)(Vg + vrow[j] + 8);
                    }
#pragma unroll
                    for (int j = 0; j < 4; j++) mma_f16(acc[g][j], a, b[j]);
                }
            }

            // ---- K-split reduction (smem) ----
            if (ks == 0) {
#pragma unroll
                for (int g = 0; g < 3; g++)
#pragma unroll
                    for (int j = 0; j < 4; j++)
#pragma unroll
                        for (int q = 0; q < 4; q++)
                            red[mf][lane][((g << 2) + j << 2) + q] = acc[g][j][q];
            }
            __syncthreads();
            if (ks != 0) {
#pragma unroll
                for (int g = 0; g < 3; g++)
#pragma unroll
                    for (int j = 0; j < 4; j++)
#pragma unroll
                        for (int q = 0; q < 4; q++)
                            atomicAdd(&red[mf][lane][((g << 2) + j << 2) + q], acc[g][j][q]);
            }
            __syncthreads();

            // ---- fused LSTM epilogue: warp (mf, jg) handles m16 x n8 ----
            {
                int colb = n0 + (jg << 3) + t2;
#pragma unroll
                for (int rh = 0; rh < 2; rh++) {
                    int m = (mf << 4) + g8 + (rh << 3);
                    if (mrel + m < cnt) {
                        int irow = s_irow[m], prow = s_prow[m], bn = s_bn[m];
                        float2 F0 = *(const float2*)(g_inp0f + bn + colb);
                        float2 O0 = *(const float2*)(g_inp0o + bn + colb);
                        float2 Z0 = *(const float2*)(g_inp0z + bn + colb);
                        float2 PC = *(const float2*)(g_tree_c + prow + colb);
                        int base = (jg << 2) + (rh << 1);
                        float fa = red[mf][lane][(0 << 4) + base];
                        float fb = red[mf][lane][(0 << 4) + base + 1];
                        float oa = red[mf][lane][(1 << 4) + base];
                        float ob = red[mf][lane][(1 << 4) + base + 1];
                        float za = red[mf][lane][(2 << 4) + base];
                        float zb = red[mf][lane][(2 << 4) + base + 1];
                        float f1 = sigf(fa + F0.x), f2 = sigf(fb + F0.y);
                        float o1 = sigf(oa + O0.x), o2 = sigf(ob + O0.y);
                        float z1 = tanf_(za + Z0.x), z2 = tanf_(zb + Z0.y);
                        float c1 = PC.x * f1 + z1 * (1.0f - f1);
                        float c2 = PC.y * f2 + z2 * (1.0f - f2);
                        float h1 = o1 * tanf_(c1);
                        float h2 = o2 * tanf_(c2);
                        *(float2*)(tree_h + irow + colb)   = make_float2(h1, h2);
                        *(float2*)(g_tree_c + irow + colb) = make_float2(c1, c2);
                        *(__half2*)(g_hph + irow + colb)   = __floats2half2_rn(h1, h2);
                    }
                }
            }
            __syncthreads();   // protect smem meta/red before next tile
        }

        // ---- grid barrier ----
        sync_no++;
        __syncthreads();
        if (tid == 0) {
            __threadfence();
            atomicAdd(&g_bar, 1u);
            unsigned target = sync_no * RNB;
            while (*((volatile unsigned int*)&g_bar) < target) __nanosleep(64);
            __threadfence();
        }
        __syncthreads();
    }
}

// ---------------- launch ----------------
extern "C" void kernel_launch(void* const* d_in, const int* in_sizes, int n_in,
                              void* d_out, int out_size) {
    const float* emb = (const float*)d_in[0];
    const int*   conn = (const int*)d_in[1];
    const float* Wf = (const float*)d_in[3];
    const float* bf = (const float*)d_in[4];
    const float* Wo = (const float*)d_in[5];
    const float* bo = (const float*)d_in[6];
    const float* Wz = (const float*)d_in[7];
    const float* bz = (const float*)d_in[8];
    const float* Tf = (const float*)d_in[9];
    const float* To = (const float*)d_in[10];
    const float* Tz = (const float*)d_in[11];
    float* tree_h = (float*)d_out;

    setup_kernel<<<1, 512>>>(conn);                                  // launch 1
    inp0_kernel<<<128, 128>>>(emb, Wf, bf, Wo, bo, Wz, bz, tree_h);  // launch 2
    v_kernel<<<3 * NTRI, 256>>>(Tf, To, Tz);                         // launch 3
    recur_kernel<<<RNB, RNT>>>(conn, tree_h);                        // launch 4 = profiled
}

// round 12
// speedup vs baseline: 1.9168x; 1.9168x over previous
#include <cuda_runtime.h>
#include <cuda_fp16.h>
#include <cstdint>
#include <math.h>

#define BATCH 16
#define NNODE 512
#define IDIM  512
#define HDIM  1024

#define RNB 296          // persistent blocks, occupancy 2
#define RNT 256
#define STG_BYTES 40960  // per stage: A 2x(64x128B) + B 2x3x(32x128B)

// ---------------- device scratch ----------------
__device__ __half g_Vh[3u * HDIM * HDIM];         // V_g fp16 [g][n][k] (symmetric)
__device__ __half g_hph[BATCH * NNODE * HDIM];    // fp16 mirror of tree_h
__device__ float  g_inp0f[BATCH * HDIM];
__device__ float  g_inp0o[BATCH * HDIM];
__device__ float  g_inp0z[BATCH * HDIM];
__device__ float  g_tree_c[BATCH * NNODE * HDIM];
__device__ int    g_sched[BATCH * NNODE];
__device__ int    g_level_off[NNODE + 1];
__device__ int    g_num_levels;
__device__ unsigned int g_bar;

// ---------------- helpers ----------------
__device__ __forceinline__ void mma_tf32(float* d, const uint32_t* a, const uint32_t* b) {
    asm volatile(
        "mma.sync.aligned.m16n8k8.row.col.f32.tf32.tf32.f32 "
        "{%0,%1,%2,%3}, {%4,%5,%6,%7}, {%8,%9}, {%0,%1,%2,%3};\n"
        : "+f"(d[0]), "+f"(d[1]), "+f"(d[2]), "+f"(d[3])
        : "r"(a[0]), "r"(a[1]), "r"(a[2]), "r"(a[3]), "r"(b[0]), "r"(b[1]));
}
__device__ __forceinline__ void mma_f16(float* d, const uint32_t* a, const uint32_t* b) {
    asm volatile(
        "mma.sync.aligned.m16n8k16.row.col.f32.f16.f16.f32 "
        "{%0,%1,%2,%3}, {%4,%5,%6,%7}, {%8,%9}, {%0,%1,%2,%3};\n"
        : "+f"(d[0]), "+f"(d[1]), "+f"(d[2]), "+f"(d[3])
        : "r"(a[0]), "r"(a[1]), "r"(a[2]), "r"(a[3]), "r"(b[0]), "r"(b[1]));
}
__device__ __forceinline__ void ldsm_x4(uint32_t* r, uint32_t addr) {
    asm volatile("ldmatrix.sync.aligned.m8n8.x4.shared.b16 {%0,%1,%2,%3}, [%4];"
        : "=r"(r[0]), "=r"(r[1]), "=r"(r[2]), "=r"(r[3]) : "r"(addr));
}
#define CP_ASYNC16(dst_u32, src_ptr) \
    asm volatile("cp.async.cg.shared.global [%0], [%1], 16;" :: "r"(dst_u32), "l"(src_ptr))
#define CP_COMMIT() asm volatile("cp.async.commit_group;" ::: "memory")
#define CP_WAIT(n)  asm volatile("cp.async.wait_group %0;" :: "n"(n) : "memory")

__device__ __forceinline__ float sigf(float x) {
    return __fdividef(1.0f, 1.0f + __expf(-x));
}
__device__ __forceinline__ float tanf_(float x) {
    return 1.0f - __fdividef(2.0f, 1.0f + __expf(2.0f * x));
}

// ---------------- setup: reset + levels + counting sort ----------------
__global__ void setup_kernel(const int* __restrict__ conn) {
    __shared__ unsigned short lvl[BATCH][NNODE];
    __shared__ int counts[NNODE];
    __shared__ int offs[NNODE + 1];
    __shared__ int cur[NNODE];
    int tid = threadIdx.x;
    if (tid == 0) g_bar = 0u;
    for (int l = tid; l < NNODE; l += blockDim.x) counts[l] = 0;
    __syncthreads();
    if (tid < BATCH) {
        int b = tid;
        lvl[b][0] = 0;
        for (int i = 1; i < NNODE; i++) {
            int p = conn[b * NNODE + i];
            lvl[b][i] = (unsigned short)(lvl[b][p] + 1);
        }
    }
    __syncthreads();
    for (int t = tid; t < BATCH * NNODE; t += blockDim.x) {
        int i = t & (NNODE - 1);
        if (i != 0) atomicAdd(&counts[lvl[t >> 9][i]], 1);
    }
    __syncthreads();
    if (tid == 0) {
        int acc = 0, maxl = 0;
        for (int l = 0; l < NNODE; l++) {
            offs[l] = acc;
            acc += counts[l];
            if (counts[l] > 0) maxl = l;
        }
        offs[NNODE] = acc;
        g_num_levels = maxl + 1;
    }
    __syncthreads();
    for (int l = tid; l <= NNODE; l += blockDim.x) g_level_off[l] = offs[l];
    for (int l = tid; l < NNODE; l += blockDim.x) cur[l] = offs[l];
    __syncthreads();
    for (int t = tid; t < BATCH * NNODE; t += blockDim.x) {
        int b = t >> 9, i = t & (NNODE - 1);
        if (i != 0) {
            int pos = atomicAdd(&cur[lvl[b][i]], 1);
            g_sched[pos] = (b << 16) | i;
        }
    }
}

// ---------------- inp0 (only node 0 matters) + roots ----------------
__global__ void inp0_kernel(const float* __restrict__ emb,
                            const float* __restrict__ Wf, const float* __restrict__ bf,
                            const float* __restrict__ Wo, const float* __restrict__ bo,
                            const float* __restrict__ Wz, const float* __restrict__ bz,
                            float* __restrict__ tree_h) {
    int t = blockIdx.x * blockDim.x + threadIdx.x;
    int b = t >> 10, n = t & (HDIM - 1);
    const float* x = emb + (size_t)b * NNODE * IDIM;
    float af = bf[n], ao = bo[n], az = bz[n];
#pragma unroll 8
    for (int k = 0; k < IDIM; k++) {
        float xv = __ldg(&x[k]);
        af = fmaf(xv, Wf[k * HDIM + n], af);
        ao = fmaf(xv, Wo[k * HDIM + n], ao);
        az = fmaf(xv, Wz[k * HDIM + n], az);
    }
    g_inp0f[t] = af; g_inp0o[t] = ao; g_inp0z[t] = az;
    float f = 1.0f / (1.0f + expf(-af));
    float o = 1.0f / (1.0f + expf(-ao));
    float z = tanhf(az);
    float c = z * (1.0f - f);
    float h = o * tanhf(c);
    int row = (b * NNODE) << 10;
    tree_h[row + n] = h;
    g_hph[row + n] = __float2half(h);
    g_tree_c[row + n] = c;
}

// ---------------- V = T^T T, upper-triangular tiles + mirror ----------------
#define NTRI 136
__global__ void v_kernel(const float* __restrict__ Tf,
                         const float* __restrict__ To,
                         const float* __restrict__ Tz) {
    __shared__ float Ats[32][68];
    __shared__ float Bts[32][68];
    int bid = blockIdx.x;
    int g = bid / NTRI;
    int t = bid - g * NTRI;
    int ti = 0;
    while (t >= 16 - ti) { t -= 16 - ti; ti++; }
    int tj = ti + t;
    int m0 = ti << 6, n0 = tj << 6;
    const float* T = (g == 0) ? Tf : (g == 1) ? To : Tz;
    int tid = threadIdx.x, lane = tid & 31, wid = tid >> 5;
    int moff = (wid >> 2) << 5, noff = (wid & 3) << 4;

    float acc[2][2][4];
#pragma unroll
    for (int mf = 0; mf < 2; mf++)
#pragma unroll
        for (int nf = 0; nf < 2; nf++)
#pragma unroll
            for (int j = 0; j < 4; j++) acc[mf][nf][j] = 0.0f;

    for (int k0 = 0; k0 < HDIM; k0 += 32) {
#pragma unroll
        for (int q = 0; q < 2; q++) {
            int fi = tid + (q << 8);
            int kk = fi >> 4, c4 = fi & 15;
            const float* rowp = T + (size_t)(k0 + kk) * HDIM;
            *(float4*)&Ats[kk][c4 << 2] = *(const float4*)(rowp + m0 + (c4 << 2));
            *(float4*)&Bts[kk][c4 << 2] = *(const float4*)(rowp + n0 + (c4 << 2));
        }
        __syncthreads();
#pragma unroll
        for (int ks = 0; ks < 4; ks++) {
            int kb = ks << 3;
            uint32_t a[2][4], b[2][2];
#pragma unroll
            for (int mf = 0; mf < 2; mf++)
#pragma unroll
                for (int i = 0; i < 4; i++) {
                    int m = moff + (mf << 4) + (lane >> 2) + ((i & 1) << 3);
                    int k = kb + (lane & 3) + ((i >> 1) << 2);
                    a[mf][i] = __float_as_uint(Ats[k][m]);
                }
#pragma unroll
            for (int nf = 0; nf < 2; nf++)
#pragma unroll
                for (int i = 0; i < 2; i++) {
                    int n = noff + (nf << 3) + (lane >> 2);
                    int k = kb + (lane & 3) + (i << 2);
                    b[nf][i] = __float_as_uint(Bts[k][n]);
                }
#pragma unroll
            for (int mf = 0; mf < 2; mf++)
#pragma unroll
                for (int nf = 0; nf < 2; nf++)
                    mma_tf32(acc[mf][nf], a[mf], b[nf]);
        }
        __syncthreads();
    }
    size_t gb = (size_t)g << 20;
#pragma unroll
    for (int mf = 0; mf < 2; mf++)
#pragma unroll
        for (int nf = 0; nf < 2; nf++)
#pragma unroll
            for (int rh = 0; rh < 2; rh++) {
                int m = m0 + moff + (mf << 4) + (lane >> 2) + (rh << 3);
                int n = n0 + noff + (nf << 3) + ((lane & 3) << 1);
                float v0 = acc[mf][nf][rh << 1], v1 = acc[mf][nf][(rh << 1) + 1];
                *(__half2*)&g_Vh[gb + ((size_t)m << 10) + n] = __floats2half2_rn(v0, v1);
                if (ti != tj) {
                    g_Vh[gb + ((size_t)n << 10) + m]       = __float2half(v0);
                    g_Vh[gb + ((size_t)(n + 1) << 10) + m] = __float2half(v1);
                }
            }
}

// ---------------- persistent recurrence: M=64 x N=32, warp = (mg, K-half) ----
// Each warp: m16 x n32 x 3 gates over K=512 -> 8 chunk iterations (vs 16).
// Pair reduction via smem stores (reuses stage0 buffer). 2-stage cp.async pipe.
__global__ void __launch_bounds__(RNT, 2)
recur_kernel(const int* __restrict__ conn, float* __restrict__ tree_h) {
    extern __shared__ __half smh[];
    __shared__ int s_prow[64];
    __shared__ int s_irow[64];
    __shared__ int s_bn[64];
    uint32_t smb = (uint32_t)__cvta_generic_to_shared(smh);

    int tid = threadIdx.x, lane = tid & 31, wid = tid >> 5;
    int mg = wid & 3, kh = wid >> 2;
    int moff = mg << 4;
    int g8 = lane >> 2, t2 = (lane & 3) << 1;

    // ldmatrix lane roles
    int t4 = lane >> 3, r8 = lane & 7;
    int arow = moff + ((t4 & 1) << 3) + r8;
    int a_chi = t4 >> 1;
    uint32_t aoff = (uint32_t)((kh << 13) + (arow << 7));
    int asw = arow & 7;
    int brow0 = ((t4 >> 1) << 3) + r8;        // nf=0 rows 0..15
    int brow1 = brow0 + 16;                   // nf=1 rows 16..31
    int b_chi = t4 & 1;
    uint32_t boff0 = (uint32_t)(brow0 << 7);
    uint32_t boff1 = (uint32_t)(brow1 << 7);
    int bsw0 = brow0 & 7, bsw1 = brow1 & 7;
    int kh3 = kh * 3;

    int num_lv = g_num_levels;
    unsigned sync_no = 0;

    for (int lv = 1; lv < num_lv; lv++) {
        int off = g_level_off[lv];
        int cnt = g_level_off[lv + 1] - off;
        int mtiles = (cnt + 63) >> 6;
        int total = mtiles << 5;                 // x 32 column slices of 32

        for (int t = blockIdx.x; t < total; t += RNB) {
            int mt = t >> 5, nt = t & 31;
            int n0 = nt << 5;
            int mrel = mt << 6;

            if (tid < 64) {
                int mi = off + mrel + tid;
                int mclamp = off + cnt - 1;
                if (mi > mclamp) mi = mclamp;
                int s = g_sched[mi];
                int b = s >> 16, i = s & 0xFFFF;
                int p = conn[(b << 9) + i];
                s_prow[tid] = ((b << 9) + p) << 10;
                s_irow[tid] = ((b << 9) + i) << 10;
                s_bn[tid]   = b << 10;
            }
            __syncthreads();

            float acc[3][4][4];
#pragma unroll
            for (int g = 0; g < 3; g++)
#pragma unroll
                for (int j = 0; j < 4; j++)
#pragma unroll
                    for (int q = 0; q < 4; q++) acc[g][j][q] = 0.0f;

            // stage loader: A 1024 + B 1536 16B-chunks (both K-halves)
#define LOAD_STAGE(st, kc_) do {                                                       \
    int kb_ = (kc_) << 6;                                                              \
    uint32_t sbase = smb + (uint32_t)(st) * STG_BYTES;                                 \
    _Pragma("unroll")                                                                  \
    for (int q = 0; q < 4; q++) {                                                      \
        int idx = tid + (q << 8);                                                      \
        int half = idx >> 9, rem = idx & 511;                                          \
        int row = rem >> 3, c16 = rem & 7;                                             \
        CP_ASYNC16(sbase + (uint32_t)((half << 13) + (row << 7)                        \
                      + ((c16 ^ (row & 7)) << 4)),                                     \
                   g_hph + s_prow[row] + (half << 9) + kb_ + (c16 << 3));              \
    }                                                                                  \
    _Pragma("unroll")                                                                  \
    for (int q = 0; q < 6; q++) {                                                      \
        int idx = tid + (q << 8);                                                      \
        int hg = idx >> 8;                                                             \
        int khh = (hg >= 3) ? 1 : 0;                                                   \
        int gg = hg - khh * 3;                                                         \
        int rem = idx & 255;                                                           \
        int row = rem >> 3, c16 = rem & 7;                                             \
        CP_ASYNC16(sbase + (uint32_t)(16384 + (hg << 12) + (row << 7)                  \
                      + ((c16 ^ (row & 7)) << 4)),                                     \
                   g_Vh + ((size_t)gg << 20) + ((size_t)(n0 + row) << 10)              \
                        + (khh << 9) + kb_ + (c16 << 3));                              \
    }                                                                                  \
    CP_COMMIT();                                                                       \
} while (0)

            LOAD_STAGE(0, 0);

            for (int it = 0; it < 8; it++) {
                CP_WAIT(0);
                __syncthreads();
                if (it + 1 < 8) LOAD_STAGE((it + 1) & 1, it + 1);

                uint32_t sb = smb + (uint32_t)(it & 1) * STG_BYTES;
#pragma unroll
                for (int ks = 0; ks < 4; ks++) {
                    int ks2 = ks << 1;
                    uint32_t a[4];
                    ldsm_x4(a, sb + aoff + (uint32_t)(((ks2 + a_chi) ^ asw) << 4));
#pragma unroll
                    for (int g = 0; g < 3; g++) {
                        uint32_t bb = sb + (uint32_t)(16384 + ((kh3 + g) << 12));
                        uint32_t b0[4], b1[4];
                        ldsm_x4(b0, bb + boff0 + (uint32_t)(((ks2 + b_chi) ^ bsw0) << 4));
                        mma_f16(acc[g][0], a, b0);
                        mma_f16(acc[g][1], a, b0 + 2);
                        ldsm_x4(b1, bb + boff1 + (uint32_t)(((ks2 + b_chi) ^ bsw1) << 4));
                        mma_f16(acc[g][2], a, b1);
                        mma_f16(acc[g][3], a, b1 + 2);
                    }
                }
            }

            // ---- K-pair reduction via smem stores (reuse stage0 buffer) ----
            float* red = (float*)smh;            // 4*32*49*4 = 25 KB <= 40 KB
            if (kh == 1) {
                float* rp = red + (mg * 32 + lane) * 49;
#pragma unroll
                for (int g = 0; g < 3; g++)
#pragma unroll
                    for (int j = 0; j < 4; j++)
#pragma unroll
                        for (int q = 0; q < 4; q++)
                            rp[g * 16 + j * 4 + q] = acc[g][j][q];
            }
            __syncthreads();

            if (kh == 0) {
                float* rp = red + (mg * 32 + lane) * 49;
#pragma unroll
                for (int g = 0; g < 3; g++)
#pragma unroll
                    for (int j = 0; j < 4; j++)
#pragma unroll
                        for (int q = 0; q < 4; q++)
                            acc[g][j][q] += rp[g * 16 + j * 4 + q];

                // ---- fused LSTM epilogue (kh0 warps: m16 x n32 each) ----
#pragma unroll
                for (int rh = 0; rh < 2; rh++) {
                    int m = moff + g8 + (rh << 3);
                    if (mrel + m < cnt) {
                        int irow = s_irow[m], prow = s_prow[m], bn = s_bn[m];
#pragma unroll
                        for (int j = 0; j < 4; j++) {
                            int col = n0 + (j << 3) + t2;
                            float2 F0 = *(const float2*)(g_inp0f + bn + col);
                            float2 O0 = *(const float2*)(g_inp0o + bn + col);
                            float2 Z0 = *(const float2*)(g_inp0z + bn + col);
                            float2 PC = *(const float2*)(g_tree_c + prow + col);
                            float fa = acc[0][j][rh << 1], fb = acc[0][j][(rh << 1) + 1];
                            float oa = acc[1][j][rh << 1], ob = acc[1][j][(rh << 1) + 1];
                            float za = acc[2][j][rh << 1], zb = acc[2][j][(rh << 1) + 1];
                            float f1 = sigf(fa + F0.x), f2 = sigf(fb + F0.y);
                            float o1 = sigf(oa + O0.x), o2 = sigf(ob + O0.y);
                            float z1 = tanf_(za + Z0.x), z2 = tanf_(zb + Z0.y);
                            float c1 = PC.x * f1 + z1 * (1.0f - f1);
                            float c2 = PC.y * f2 + z2 * (1.0f - f2);
                            float h1 = o1 * tanf_(c1);
                            float h2 = o2 * tanf_(c2);
                            *(float2*)(tree_h + irow + col)   = make_float2(h1, h2);
                            *(float2*)(g_tree_c + irow + col) = make_float2(c1, c2);
                            *(__half2*)(g_hph + irow + col)   = __floats2half2_rn(h1, h2);
                        }
                    }
                }
            }
            __syncthreads();   // protect meta + stage0/red before next tile
        }

        // ---- grid barrier (tight poll, no nanosleep) ----
        sync_no++;
        __syncthreads();
        if (tid == 0) {
            __threadfence();
            atomicAdd(&g_bar, 1u);
            unsigned target = sync_no * RNB;
            while (*((volatile unsigned int*)&g_bar) < target) {}
            __threadfence();
        }
        __syncthreads();
    }
}

// ---------------- launch ----------------
#define SMEM_RECUR (2 * STG_BYTES)

extern "C" void kernel_launch(void* const* d_in, const int* in_sizes, int n_in,
                              void* d_out, int out_size) {
    const float* emb = (const float*)d_in[0];
    const int*   conn = (const int*)d_in[1];
    const float* Wf = (const float*)d_in[3];
    const float* bf = (const float*)d_in[4];
    const float* Wo = (const float*)d_in[5];
    const float* bo = (const float*)d_in[6];
    const float* Wz = (const float*)d_in[7];
    const float* bz = (const float*)d_in[8];
    const float* Tf = (const float*)d_in[9];
    const float* To = (const float*)d_in[10];
    const float* Tz = (const float*)d_in[11];
    float* tree_h = (float*)d_out;

    cudaFuncSetAttribute(recur_kernel, cudaFuncAttributeMaxDynamicSharedMemorySize, SMEM_RECUR);

    setup_kernel<<<1, 512>>>(conn);                                  // launch 1
    inp0_kernel<<<128, 128>>>(emb, Wf, bf, Wo, bo, Wz, bz, tree_h);  // launch 2
    v_kernel<<<3 * NTRI, 256>>>(Tf, To, Tz);                         // launch 3
    recur_kernel<<<RNB, RNT, SMEM_RECUR>>>(conn, tree_h);            // launch 4 = profiled
}

// round 13
// speedup vs baseline: 2.1450x; 1.1191x over previous
#include <cuda_runtime.h>
#include <cuda_fp16.h>
#include <cstdint>
#include <math.h>

#define BATCH 16
#define NNODE 512
#define IDIM  512
#define HDIM  1024

#define RNB 296          // persistent blocks, occupancy 2
#define RNT 256
#define NKC 16           // wide path: 16 k-chunks of 64 halves
#define STAGE_BYTES 20480    // wide stage: A(8KB) + 3x B(4KB), swizzled

// ---------------- device scratch ----------------
__device__ __half g_Vh[3u * HDIM * HDIM];         // V_g fp16 [g][n][k] (symmetric)
__device__ __half g_hph[BATCH * NNODE * HDIM];    // fp16 mirror of tree_h
__device__ float  g_inp0f[BATCH * HDIM];
__device__ float  g_inp0o[BATCH * HDIM];
__device__ float  g_inp0z[BATCH * HDIM];
__device__ float  g_tree_c[BATCH * NNODE * HDIM];
__device__ int    g_sched[BATCH * NNODE];
__device__ int    g_level_off[NNODE + 1];
__device__ int    g_num_levels;
__device__ unsigned int g_bar;

// ---------------- helpers ----------------
__device__ __forceinline__ void mma_tf32(float* d, const uint32_t* a, const uint32_t* b) {
    asm volatile(
        "mma.sync.aligned.m16n8k8.row.col.f32.tf32.tf32.f32 "
        "{%0,%1,%2,%3}, {%4,%5,%6,%7}, {%8,%9}, {%0,%1,%2,%3};\n"
        : "+f"(d[0]), "+f"(d[1]), "+f"(d[2]), "+f"(d[3])
        : "r"(a[0]), "r"(a[1]), "r"(a[2]), "r"(a[3]), "r"(b[0]), "r"(b[1]));
}
__device__ __forceinline__ void mma_f16(float* d, const uint32_t* a, const uint32_t* b) {
    asm volatile(
        "mma.sync.aligned.m16n8k16.row.col.f32.f16.f16.f32 "
        "{%0,%1,%2,%3}, {%4,%5,%6,%7}, {%8,%9}, {%0,%1,%2,%3};\n"
        : "+f"(d[0]), "+f"(d[1]), "+f"(d[2]), "+f"(d[3])
        : "r"(a[0]), "r"(a[1]), "r"(a[2]), "r"(a[3]), "r"(b[0]), "r"(b[1]));
}
__device__ __forceinline__ void ldsm_x4(uint32_t* r, uint32_t addr) {
    asm volatile("ldmatrix.sync.aligned.m8n8.x4.shared.b16 {%0,%1,%2,%3}, [%4];"
        : "=r"(r[0]), "=r"(r[1]), "=r"(r[2]), "=r"(r[3]) : "r"(addr));
}
#define CP_ASYNC16(dst_u32, src_ptr) \
    asm volatile("cp.async.cg.shared.global [%0], [%1], 16;" :: "r"(dst_u32), "l"(src_ptr))
#define CP_COMMIT() asm volatile("cp.async.commit_group;" ::: "memory")
#define CP_WAIT(n)  asm volatile("cp.async.wait_group %0;" :: "n"(n) : "memory")

__device__ __forceinline__ float sigf(float x) {
    return __fdividef(1.0f, 1.0f + __expf(-x));
}
__device__ __forceinline__ float tanf_(float x) {
    return 1.0f - __fdividef(2.0f, 1.0f + __expf(2.0f * x));
}

// ---------------- setup: reset + levels + counting sort ----------------
__global__ void setup_kernel(const int* __restrict__ conn) {
    __shared__ unsigned short lvl[BATCH][NNODE];
    __shared__ int counts[NNODE];
    __shared__ int offs[NNODE + 1];
    __shared__ int cur[NNODE];
    int tid = threadIdx.x;
    if (tid == 0) g_bar = 0u;
    for (int l = tid; l < NNODE; l += blockDim.x) counts[l] = 0;
    __syncthreads();
    if (tid < BATCH) {
        int b = tid;
        lvl[b][0] = 0;
        for (int i = 1; i < NNODE; i++) {
            int p = conn[b * NNODE + i];
            lvl[b][i] = (unsigned short)(lvl[b][p] + 1);
        }
    }
    __syncthreads();
    for (int t = tid; t < BATCH * NNODE; t += blockDim.x) {
        int i = t & (NNODE - 1);
        if (i != 0) atomicAdd(&counts[lvl[t >> 9][i]], 1);
    }
    __syncthreads();
    if (tid == 0) {
        int acc = 0, maxl = 0;
        for (int l = 0; l < NNODE; l++) {
            offs[l] = acc;
            acc += counts[l];
            if (counts[l] > 0) maxl = l;
        }
        offs[NNODE] = acc;
        g_num_levels = maxl + 1;
    }
    __syncthreads();
    for (int l = tid; l <= NNODE; l += blockDim.x) g_level_off[l] = offs[l];
    for (int l = tid; l < NNODE; l += blockDim.x) cur[l] = offs[l];
    __syncthreads();
    for (int t = tid; t < BATCH * NNODE; t += blockDim.x) {
        int b = t >> 9, i = t & (NNODE - 1);
        if (i != 0) {
            int pos = atomicAdd(&cur[lvl[b][i]], 1);
            g_sched[pos] = (b << 16) | i;
        }
    }
}

// ---------------- inp0 (only node 0 matters) + roots ----------------
__global__ void inp0_kernel(const float* __restrict__ emb,
                            const float* __restrict__ Wf, const float* __restrict__ bf,
                            const float* __restrict__ Wo, const float* __restrict__ bo,
                            const float* __restrict__ Wz, const float* __restrict__ bz,
                            float* __restrict__ tree_h) {
    int t = blockIdx.x * blockDim.x + threadIdx.x;
    int b = t >> 10, n = t & (HDIM - 1);
    const float* x = emb + (size_t)b * NNODE * IDIM;
    float af = bf[n], ao = bo[n], az = bz[n];
#pragma unroll 8
    for (int k = 0; k < IDIM; k++) {
        float xv = __ldg(&x[k]);
        af = fmaf(xv, Wf[k * HDIM + n], af);
        ao = fmaf(xv, Wo[k * HDIM + n], ao);
        az = fmaf(xv, Wz[k * HDIM + n], az);
    }
    g_inp0f[t] = af; g_inp0o[t] = ao; g_inp0z[t] = az;
    float f = 1.0f / (1.0f + expf(-af));
    float o = 1.0f / (1.0f + expf(-ao));
    float z = tanhf(az);
    float c = z * (1.0f - f);
    float h = o * tanhf(c);
    int row = (b * NNODE) << 10;
    tree_h[row + n] = h;
    g_hph[row + n] = __float2half(h);
    g_tree_c[row + n] = c;
}

// ---------------- V = T^T T, upper-triangular tiles + mirror ----------------
#define NTRI 136
__global__ void v_kernel(const float* __restrict__ Tf,
                         const float* __restrict__ To,
                         const float* __restrict__ Tz) {
    __shared__ float Ats[32][68];
    __shared__ float Bts[32][68];
    int bid = blockIdx.x;
    int g = bid / NTRI;
    int t = bid - g * NTRI;
    int ti = 0;
    while (t >= 16 - ti) { t -= 16 - ti; ti++; }
    int tj = ti + t;
    int m0 = ti << 6, n0 = tj << 6;
    const float* T = (g == 0) ? Tf : (g == 1) ? To : Tz;
    int tid = threadIdx.x, lane = tid & 31, wid = tid >> 5;
    int moff = (wid >> 2) << 5, noff = (wid & 3) << 4;

    float acc[2][2][4];
#pragma unroll
    for (int mf = 0; mf < 2; mf++)
#pragma unroll
        for (int nf = 0; nf < 2; nf++)
#pragma unroll
            for (int j = 0; j < 4; j++) acc[mf][nf][j] = 0.0f;

    for (int k0 = 0; k0 < HDIM; k0 += 32) {
#pragma unroll
        for (int q = 0; q < 2; q++) {
            int fi = tid + (q << 8);
            int kk = fi >> 4, c4 = fi & 15;
            const float* rowp = T + (size_t)(k0 + kk) * HDIM;
            *(float4*)&Ats[kk][c4 << 2] = *(const float4*)(rowp + m0 + (c4 << 2));
            *(float4*)&Bts[kk][c4 << 2] = *(const float4*)(rowp + n0 + (c4 << 2));
        }
        __syncthreads();
#pragma unroll
        for (int ks = 0; ks < 4; ks++) {
            int kb = ks << 3;
            uint32_t a[2][4], b[2][2];
#pragma unroll
            for (int mf = 0; mf < 2; mf++)
#pragma unroll
                for (int i = 0; i < 4; i++) {
                    int m = moff + (mf << 4) + (lane >> 2) + ((i & 1) << 3);
                    int k = kb + (lane & 3) + ((i >> 1) << 2);
                    a[mf][i] = __float_as_uint(Ats[k][m]);
                }
#pragma unroll
            for (int nf = 0; nf < 2; nf++)
#pragma unroll
                for (int i = 0; i < 2; i++) {
                    int n = noff + (nf << 3) + (lane >> 2);
                    int k = kb + (lane & 3) + (i << 2);
                    b[nf][i] = __float_as_uint(Bts[k][n]);
                }
#pragma unroll
            for (int mf = 0; mf < 2; mf++)
#pragma unroll
                for (int nf = 0; nf < 2; nf++)
                    mma_tf32(acc[mf][nf], a[mf], b[nf]);
        }
        __syncthreads();
    }
    size_t gb = (size_t)g << 20;
#pragma unroll
    for (int mf = 0; mf < 2; mf++)
#pragma unroll
        for (int nf = 0; nf < 2; nf++)
#pragma unroll
            for (int rh = 0; rh < 2; rh++) {
                int m = m0 + moff + (mf << 4) + (lane >> 2) + (rh << 3);
                int n = n0 + noff + (nf << 3) + ((lane & 3) << 1);
                float v0 = acc[mf][nf][rh << 1], v1 = acc[mf][nf][(rh << 1) + 1];
                *(__half2*)&g_Vh[gb + ((size_t)m << 10) + n] = __floats2half2_rn(v0, v1);
                if (ti != tj) {
                    g_Vh[gb + ((size_t)n << 10) + m]       = __float2half(v0);
                    g_Vh[gb + ((size_t)(n + 1) << 10) + m] = __float2half(v1);
                }
            }
}

// ---------------- persistent recurrence -------------------------------------
// Wide path (cnt>32): R10 M=64 x N=32 smem/ldmatrix tiles, 4-stage pipeline.
// Narrow path (cnt<=32): one-shot m16 x n8 x 3g tiles, direct-LDG fragments,
// K split over 8 warps, smem-store reduction, warp-0 fused epilogue.
__global__ void __launch_bounds__(RNT, 2)
recur_kernel(const int* __restrict__ conn, float* __restrict__ tree_h) {
    extern __shared__ __half smh[];
    int* s_prow = (int*)(smh + 4 * (STAGE_BYTES / 2));
    int* s_irow = s_prow + 64;
    int* s_bn   = s_prow + 128;
    uint32_t smb = (uint32_t)__cvta_generic_to_shared(smh);

    int tid = threadIdx.x, lane = tid & 31, wid = tid >> 5;
    int moff = (wid >> 1) << 4;          // wide: 0,16,32,48
    int noff_w = (wid & 1) << 4;         // wide: 0,16
    int g8 = lane >> 2, t2 = (lane & 3) << 1;

    // wide-path ldmatrix lane roles
    int t4 = lane >> 3, r8 = lane & 7;
    int arow = moff + ((t4 & 1) << 3) + r8;
    int a_chi = t4 >> 1;
    int brow = noff_w + ((t4 >> 1) << 3) + r8;
    int b_chi = t4 & 1;
    uint32_t aoff = (uint32_t)(arow << 7);
    int asw = arow & 7;
    uint32_t boff = (uint32_t)(brow << 7);
    int bsw = brow & 7;
    int loader_r = tid >> 3, loader_c16 = tid & 7;

    int num_lv = g_num_levels;
    unsigned sync_no = 0;

    for (int lv = 1; lv < num_lv; lv++) {
        int off = g_level_off[lv];
        int cnt = g_level_off[lv + 1] - off;

        if (cnt > 32) {
            // ==================== WIDE PATH (R10) ====================
            int mtiles = (cnt + 63) >> 6;
            int total = mtiles << 5;

            for (int t = blockIdx.x; t < total; t += RNB) {
                int mt = t >> 5, nt = t & 31;
                int n0 = nt << 5;
                int mrel = mt << 6;

                if (tid < 64) {
                    int mi = off + mrel + tid;
                    int mclamp = off + cnt - 1;
                    if (mi > mclamp) mi = mclamp;
                    int s = g_sched[mi];
                    int b = s >> 16, i = s & 0xFFFF;
                    int p = conn[(b << 9) + i];
                    s_prow[tid] = ((b << 9) + p) << 10;
                    s_irow[tid] = ((b << 9) + i) << 10;
                    s_bn[tid]   = b << 10;
                }
                __syncthreads();

                // epilogue prefetch
                int em0 = moff + g8, em1 = moff + g8 + 8;
                int eprow0 = s_prow[em0], eprow1 = s_prow[em1];
                int ebn0 = s_bn[em0], ebn1 = s_bn[em1];
                float2 PCp[2][2];
#pragma unroll
                for (int nf = 0; nf < 2; nf++) {
                    int col = n0 + noff_w + (nf << 3) + t2;
                    PCp[0][nf] = *(const float2*)(g_tree_c + eprow0 + col);
                    PCp[1][nf] = *(const float2*)(g_tree_c + eprow1 + col);
                }

                float acc[3][2][4];
#pragma unroll
                for (int g = 0; g < 3; g++)
#pragma unroll
                    for (int nf = 0; nf < 2; nf++)
#pragma unroll
                        for (int j = 0; j < 4; j++) acc[g][nf][j] = 0.0f;

#define LOAD_STAGE(st, kc_) do {                                                       \
    int kb_ = (kc_) << 6;                                                              \
    uint32_t sbase = smb + (uint32_t)(st) * STAGE_BYTES;                               \
    _Pragma("unroll")                                                                  \
    for (int q = 0; q < 2; q++) {                                                      \
        int r = (q << 5) + loader_r;                                                   \
        CP_ASYNC16(sbase + (uint32_t)((r << 7) + ((loader_c16 ^ (r & 7)) << 4)),       \
                   g_hph + s_prow[r] + kb_ + (loader_c16 << 3));                       \
    }                                                                                  \
    _Pragma("unroll")                                                                  \
    for (int g = 0; g < 3; g++) {                                                      \
        int r = tid >> 3;                                                              \
        CP_ASYNC16(sbase + (uint32_t)(8192 + (g << 12) + (r << 7)                      \
                      + ((loader_c16 ^ (r & 7)) << 4)),                                \
                   g_Vh + ((size_t)g << 20) + ((size_t)(n0 + r) << 10)                 \
                        + kb_ + (loader_c16 << 3));                                    \
    }                                                                                  \
    CP_COMMIT();                                                                       \
} while (0)

                LOAD_STAGE(0, 0);
                LOAD_STAGE(1, 1);
                LOAD_STAGE(2, 2);

                for (int kc = 0; kc < NKC; kc++) {
                    int rem = NKC - 1 - kc;
                    if (rem >= 2) { CP_WAIT(2); }
                    else if (rem == 1) { CP_WAIT(1); }
                    else { CP_WAIT(0); }
                    __syncthreads();
                    if (kc + 3 < NKC) LOAD_STAGE((kc + 3) & 3, kc + 3);

                    uint32_t sb = smb + (uint32_t)(kc & 3) * STAGE_BYTES;
#pragma unroll
                    for (int ks = 0; ks < 4; ks++) {
                        int ks2 = ks << 1;
                        uint32_t a[4];
                        ldsm_x4(a, sb + aoff + (uint32_t)(((ks2 + a_chi) ^ asw) << 4));
#pragma unroll
                        for (int g = 0; g < 3; g++) {
                            uint32_t b[4];
                            ldsm_x4(b, sb + (uint32_t)(8192 + (g << 12)) + boff
                                       + (uint32_t)(((ks2 + b_chi) ^ bsw) << 4));
                            mma_f16(acc[g][0], a, b);
                            mma_f16(acc[g][1], a, b + 2);
                        }
                    }
                }

                // fused LSTM epilogue
#pragma unroll
                for (int rh = 0; rh < 2; rh++) {
                    int m = moff + g8 + (rh << 3);
                    if (mrel + m < cnt) {
                        int irow = s_irow[m];
                        int bn = rh ? ebn1 : ebn0;
#pragma unroll
                        for (int nf = 0; nf < 2; nf++) {
                            int col = n0 + noff_w + (nf << 3) + t2;
                            float2 F0 = *(const float2*)(g_inp0f + bn + col);
                            float2 O0 = *(const float2*)(g_inp0o + bn + col);
                            float2 Z0 = *(const float2*)(g_inp0z + bn + col);
                            float2 PC = PCp[rh][nf];
                            float fa = acc[0][nf][rh << 1], fb = acc[0][nf][(rh << 1) + 1];
                            float oa = acc[1][nf][rh << 1], ob = acc[1][nf][(rh << 1) + 1];
                            float za = acc[2][nf][rh << 1], zb = acc[2][nf][(rh << 1) + 1];
                            float f1 = sigf(fa + F0.x), f2 = sigf(fb + F0.y);
                            float o1 = sigf(oa + O0.x), o2 = sigf(ob + O0.y);
                            float z1 = tanf_(za + Z0.x), z2 = tanf_(zb + Z0.y);
                            float c1 = PC.x * f1 + z1 * (1.0f - f1);
                            float c2 = PC.y * f2 + z2 * (1.0f - f2);
                            float h1 = o1 * tanf_(c1);
                            float h2 = o2 * tanf_(c2);
                            *(float2*)(tree_h + irow + col)   = make_float2(h1, h2);
                            *(float2*)(g_tree_c + irow + col) = make_float2(c1, c2);
                            *(__half2*)(g_hph + irow + col)   = __floats2half2_rn(h1, h2);
                        }
                    }
                }
                __syncthreads();
            }
        } else {
            // ==================== NARROW PATH (cnt <= 32) ====================
            int mt16 = (cnt + 15) >> 4;          // 1 or 2
            int used = mt16 << 7;                // 128 or 256 CTAs
            if ((int)blockIdx.x < used) {
                int mtile = blockIdx.x >> 7, nt = blockIdx.x & 127;
                int n0 = nt << 3;                // col within gate (0..1016)
                int mrel = mtile << 4;

                if (tid < 16) {
                    int mi = off + mrel + tid;
                    int mclamp = off + cnt - 1;
                    if (mi > mclamp) mi = mclamp;
                    int s = g_sched[mi];
                    int b = s >> 16, i = s & 0xFFFF;
                    int p = conn[(b << 9) + i];
                    s_prow[tid] = ((b << 9) + p) << 10;
                    s_irow[tid] = ((b << 9) + i) << 10;
                    s_bn[tid]   = b << 10;
                }
                __syncthreads();

                int pr0 = s_prow[g8], pr1 = s_prow[g8 + 8];
                int colg = n0 + t2;

                // epilogue operand prefetch (warp 0 only)
                float2 F0a, F0b, O0a, O0b, Z0a, Z0b, PCa, PCb;
                if (wid == 0) {
                    int bna = s_bn[g8], bnb = s_bn[g8 + 8];
                    F0a = *(const float2*)(g_inp0f + bna + colg);
                    F0b = *(const float2*)(g_inp0f + bnb + colg);
                    O0a = *(const float2*)(g_inp0o + bna + colg);
                    O0b = *(const float2*)(g_inp0o + bnb + colg);
                    Z0a = *(const float2*)(g_inp0z + bna + colg);
                    Z0b = *(const float2*)(g_inp0z + bnb + colg);
                    PCa = *(const float2*)(g_tree_c + pr0 + colg);
                    PCb = *(const float2*)(g_tree_c + pr1 + colg);
                }

                float acc[3][4];
#pragma unroll
                for (int g = 0; g < 3; g++)
#pragma unroll
                    for (int q = 0; q < 4; q++) acc[g][q] = 0.0f;

                int kb0 = wid << 7;              // warp K-segment (128)
                const __half* Ap0 = g_hph + pr0 + kb0 + t2;
                const __half* Ap1 = g_hph + pr1 + kb0 + t2;
                const __half* Vp  = g_Vh + ((size_t)(n0 + g8) << 10) + kb0 + t2;

#pragma unroll 4
                for (int s = 0; s < 8; s++) {
                    int ko = s << 4;
                    uint32_t a[4];
                    a[0] = *(const uint32_t*)(Ap0 + ko);
                    a[1] = *(const uint32_t*)(Ap1 + ko);
                    a[2] = *(const uint32_t*)(Ap0 + ko + 8);
                    a[3] = *(const uint32_t*)(Ap1 + ko + 8);
#pragma unroll
                    for (int g = 0; g < 3; g++) {
                        const __half* Vg = Vp + ((size_t)g << 20) + ko;
                        uint32_t b2[2];
                        b2[0] = *(const uint32_t*)(Vg);
                        b2[1] = *(const uint32_t*)(Vg + 8);
                        mma_f16(acc[g], a, b2);
                    }
                }

                // cross-warp K reduction: warps 1..7 store, warp 0 sums
                float* red = (float*)smh;        // aliases stage buffers
                if (wid > 0) {
                    float* rp = red + (((wid - 1) << 5) + lane) * 13;
#pragma unroll
                    for (int g = 0; g < 3; g++)
#pragma unroll
                        for (int q = 0; q < 4; q++)
                            rp[(g << 2) + q] = acc[g][q];
                }
                __syncthreads();
                if (wid == 0) {
#pragma unroll
                    for (int w = 0; w < 7; w++) {
                        float* rp = red + ((w << 5) + lane) * 13;
#pragma unroll
                        for (int g = 0; g < 3; g++)
#pragma unroll
                            for (int q = 0; q < 4; q++)
                                acc[g][q] += rp[(g << 2) + q];
                    }
                    // fused LSTM epilogue
#pragma unroll
                    for (int rh = 0; rh < 2; rh++) {
                        int m = g8 + (rh << 3);
                        if (mrel + m < cnt) {
                            int irow = s_irow[m];
                            float2 F0 = rh ? F0b : F0a;
                            float2 O0 = rh ? O0b : O0a;
                            float2 Z0 = rh ? Z0b : Z0a;
                            float2 PC = rh ? PCb : PCa;
                            float fa = acc[0][rh << 1], fb = acc[0][(rh << 1) + 1];
                            float oa = acc[1][rh << 1], ob = acc[1][(rh << 1) + 1];
                            float za = acc[2][rh << 1], zb = acc[2][(rh << 1) + 1];
                            float f1 = sigf(fa + F0.x), f2 = sigf(fb + F0.y);
                            float o1 = sigf(oa + O0.x), o2 = sigf(ob + O0.y);
                            float z1 = tanf_(za + Z0.x), z2 = tanf_(zb + Z0.y);
                            float c1 = PC.x * f1 + z1 * (1.0f - f1);
                            float c2 = PC.y * f2 + z2 * (1.0f - f2);
                            float h1 = o1 * tanf_(c1);
                            float h2 = o2 * tanf_(c2);
                            *(float2*)(tree_h + irow + colg)   = make_float2(h1, h2);
                            *(float2*)(g_tree_c + irow + colg) = make_float2(c1, c2);
                            *(__half2*)(g_hph + irow + colg)   = __floats2half2_rn(h1, h2);
                        }
                    }
                }
                __syncthreads();
            }
        }

        // ---- grid barrier ----
        sync_no++;
        __syncthreads();
        if (tid == 0) {
            __threadfence();
            atomicAdd(&g_bar, 1u);
            unsigned target = sync_no * RNB;
            while (*((volatile unsigned int*)&g_bar) < target) __nanosleep(64);
            __threadfence();
        }
        __syncthreads();
    }
}

// ---------------- launch ----------------
#define SMEM_RECUR (4 * STAGE_BYTES + 192 * 4)

extern "C" void kernel_launch(void* const* d_in, const int* in_sizes, int n_in,
                              void* d_out, int out_size) {
    const float* emb = (const float*)d_in[0];
    const int*   conn = (const int*)d_in[1];
    const float* Wf = (const float*)d_in[3];
    const float* bf = (const float*)d_in[4];
    const float* Wo = (const float*)d_in[5];
    const float* bo = (const float*)d_in[6];
    const float* Wz = (const float*)d_in[7];
    const float* bz = (const float*)d_in[8];
    const float* Tf = (const float*)d_in[9];
    const float* To = (const float*)d_in[10];
    const float* Tz = (const float*)d_in[11];
    float* tree_h = (float*)d_out;

    cudaFuncSetAttribute(recur_kernel, cudaFuncAttributeMaxDynamicSharedMemorySize, SMEM_RECUR);

    setup_kernel<<<1, 512>>>(conn);                                  // launch 1
    inp0_kernel<<<128, 128>>>(emb, Wf, bf, Wo, bo, Wz, bz, tree_h);  // launch 2
    v_kernel<<<3 * NTRI, 256>>>(Tf, To, Tz);                         // launch 3
    recur_kernel<<<RNB, RNT, SMEM_RECUR>>>(conn, tree_h);            // launch 4 = profiled
}